// round 5
// baseline (speedup 1.0000x reference)
#include <cuda_runtime.h>

// Problem constants (STGNN_91242285236402): B=8, T=16, N=64, F=16, H=128
#define Bc 8
#define Tc 16
#define Nc 64
#define Fc 16
#define Hc 128
#define BN (Bc * Nc)   // 512
#define PADN 68        // padded row width for bt_sh [k][t]
#define GRID 128
#define NTHR 512

// Scratch (allocation-free: __device__ globals)
__device__ float g_a  [BN * Hc];        // a[row][k]   = node@W1s.T + b1
__device__ float g_btT[Bc * Hc * Nc];   // btT[b][k][n] = (node@W1t.T) transposed
__device__ float g_lp [BN];             // Wp . (Wgcn@node + bgcn)
__device__ unsigned g_bar = 0;          // grid barrier (monotonic, replay-safe)

union SmemU {
    struct {
        float x[8][Fc];
        float node[8][Hc];
        float wv4[4][Hc];
        float wv[Hc];
        float cb;
    } A;
    struct {
        float bt[Hc][PADN];     // 34.8 KB
        float a[4][Hc];
        float w2[Hc];
        float lp[4];
        float pr[Nc];
        float psum[2][4][Nc];   // k-half partials
    } B;
};

__device__ __forceinline__ void grid_bar()
{
    __syncthreads();
    __threadfence();
    if (threadIdx.x == 0) {
        unsigned v = atomicAdd(&g_bar, 1u);
        unsigned target = (v & ~(GRID - 1u)) + GRID;   // end of this wave
        volatile unsigned* p = &g_bar;
        while (*p < target) { }
        __threadfence();
    }
    __syncthreads();
}

// ---------------------------------------------------------------------------
// Fused kernel, 128 blocks x 512 threads (16 warps/SM, all co-resident).
// Phase A: block = (rowgroup rg = blockIdx>>1 [8 rows], bh = blockIdx&1).
//   both : node[h] = bg[h] + sum_f x*Wg          (8 x 128)
//   bh=0 : a[k]  = b1[k] + node.W1s[k] -> g_a ;  pressures init = bp
//   bh=1 : btT[b][k][n] = node.W1t[k]  -> g_btT; wvec, cb, lp -> g_lp
// Phase B: block = (b = blockIdx>>4, g = blockIdx&15 [4 src]); dense edges:
//   warp = (sl, t-half, k-half): 64-k partial -> smem; combine:
//   ew(s,t) = b2 + sum_k relu(a[s,k] + btT[k,t]) * W2[k],  e = s*63+(t-(t>s))
//   pressures[b,t] += ew * lp[s]
// ---------------------------------------------------------------------------
__global__ void __launch_bounds__(NTHR) kfused(
    const float* __restrict__ x,   const float* __restrict__ Wg,
    const float* __restrict__ bg,  const float* __restrict__ W1,
    const float* __restrict__ b1,  const float* __restrict__ W2,
    const float* __restrict__ b2,  const float* __restrict__ Wgcn,
    const float* __restrict__ bgcn,const float* __restrict__ Wp,
    const float* __restrict__ bp,  float* __restrict__ out, int E)
{
    __shared__ SmemU sm;
    const int tid = threadIdx.x;

    // ================= Phase A =================
    {
        const int bh = blockIdx.x & 1;          // 0 -> a, 1 -> btT
        const int rowbase = (blockIdx.x >> 1) * 8;

        // stage x (8 rows x 16 f)
        if (tid < 128) {
            int r = tid >> 4, f = tid & 15;
            int row = rowbase + r, b = row >> 6, n = row & 63;
            sm.A.x[r][f] = x[(((b * Tc + (Tc - 1)) * Nc + n) * Fc) + f];
        }
        if (bh == 0) {
            if (tid < 8) out[rowbase + tid] = __ldg(bp);   // pressures init
        } else {
            // wvec quarter-partials: thread (h = tid&127, kq = tid>>7)
            int h = tid & 127, kq = tid >> 7;
            float s = 0.f;
            const int k0 = kq * 32;
            #pragma unroll 8
            for (int k = 0; k < 32; k++)
                s += __ldg(&Wp[k0 + k]) * __ldg(&Wgcn[(k0 + k) * Hc + h]);
            sm.A.wv4[kq][h] = s;
            if (tid == 0) sm.A.cb = 0.f;
        }
        __syncthreads();

        // node: 8 rows x 128 h over 512 threads (2 outputs each)
        #pragma unroll
        for (int i = 0; i < 2; i++) {
            int idx = tid + i * NTHR;
            int r = idx >> 7, h = idx & 127;
            const float4* wg4 = (const float4*)(Wg + h * Fc);
            float4 w0 = __ldg(wg4 + 0), w1 = __ldg(wg4 + 1);
            float4 w2 = __ldg(wg4 + 2), w3 = __ldg(wg4 + 3);
            const float* xr = sm.A.x[r];
            float acc = __ldg(&bg[h]);
            acc += xr[0]*w0.x + xr[1]*w0.y + xr[2]*w0.z + xr[3]*w0.w;
            acc += xr[4]*w1.x + xr[5]*w1.y + xr[6]*w1.z + xr[7]*w1.w;
            acc += xr[8]*w2.x + xr[9]*w2.y + xr[10]*w2.z + xr[11]*w2.w;
            acc += xr[12]*w3.x + xr[13]*w3.y + xr[14]*w3.z + xr[15]*w3.w;
            sm.A.node[r][h] = acc;
        }
        if (bh == 1 && tid < 128) {
            // combine wvec quarters; cb reduction
            sm.A.wv[tid] = sm.A.wv4[0][tid] + sm.A.wv4[1][tid]
                         + sm.A.wv4[2][tid] + sm.A.wv4[3][tid];
            float v = __ldg(&Wp[tid]) * __ldg(&bgcn[tid]);
            #pragma unroll
            for (int o = 16; o; o >>= 1) v += __shfl_xor_sync(0xffffffffu, v, o);
            if ((tid & 31) == 0) atomicAdd(&sm.A.cb, v);
        }
        __syncthreads();

        // GEMM: 16 warps, warp w owns k in [w*8, w*8+8); 8-lane dots.
        const int lane = tid & 31, w = tid >> 5;
        const int j = lane & 7, d = lane >> 3;
        const float* Wbase = W1 + bh * Hc;
        const int kbase = w * 8;

        #pragma unroll
        for (int r = 0; r < 8; r++) {
            const float* nrow = &sm.A.node[r][j * 16];
            float4 n0 = *(const float4*)(nrow + 0);
            float4 n1 = *(const float4*)(nrow + 4);
            float4 n2 = *(const float4*)(nrow + 8);
            float4 n3 = *(const float4*)(nrow + 12);
            #pragma unroll
            for (int kk = 0; kk < 2; kk++) {
                int k = kbase + kk * 4 + d;
                const float4* wp4 = (const float4*)(Wbase + k * (2 * Hc) + j * 16);
                float4 w0 = __ldg(wp4 + 0), w1 = __ldg(wp4 + 1);
                float4 w2 = __ldg(wp4 + 2), w3 = __ldg(wp4 + 3);
                float acc = n0.x*w0.x + n0.y*w0.y + n0.z*w0.z + n0.w*w0.w
                          + n1.x*w1.x + n1.y*w1.y + n1.z*w1.z + n1.w*w1.w
                          + n2.x*w2.x + n2.y*w2.y + n2.z*w2.z + n2.w*w2.w
                          + n3.x*w3.x + n3.y*w3.y + n3.z*w3.z + n3.w*w3.w;
                acc += __shfl_xor_sync(0xffffffffu, acc, 1);
                acc += __shfl_xor_sync(0xffffffffu, acc, 2);
                acc += __shfl_xor_sync(0xffffffffu, acc, 4);
                if (j == 0) {
                    int row = rowbase + r;
                    if (bh == 0) {
                        g_a[row * Hc + k] = acc + __ldg(&b1[k]);
                    } else {
                        int b = row >> 6, n = row & 63;
                        g_btT[(b * Hc + k) * Nc + n] = acc;
                    }
                }
            }
        }

        // lp: warps 0..7 reduce rows 0..7 (bh=1 blocks only)
        if (bh == 1 && w < 8) {
            float4 n  = *(const float4*)&sm.A.node[w][lane * 4];
            float4 wv = *(const float4*)&sm.A.wv[lane * 4];
            float v = n.x*wv.x + n.y*wv.y + n.z*wv.z + n.w*wv.w;
            #pragma unroll
            for (int o = 16; o; o >>= 1) v += __shfl_xor_sync(0xffffffffu, v, o);
            if (lane == 0) g_lp[rowbase + w] = v + sm.A.cb;
        }
    }

    // ================= grid barrier =================
    grid_bar();

    // ================= Phase B =================
    {
        const int b = blockIdx.x >> 4;
        const int g = blockIdx.x & 15;

        // stage btT[b] (128 x 64) transposed-padded: 2048 float4 / 512 thr
        const float4* src4 = (const float4*)(g_btT + b * Hc * Nc);
        #pragma unroll
        for (int p = 0; p < 4; p++) {
            int q = tid + p * NTHR;
            int k = q >> 4, t4 = q & 15;
            float4 v = __ldg(src4 + q);
            *(float4*)&sm.B.bt[k][t4 * 4] = v;
        }
        if (tid < 128) {
            int sl = tid >> 5, k4 = tid & 31;
            *(float4*)&sm.B.a[sl][k4 * 4] =
                __ldg((const float4*)(g_a + (b * Nc + g * 4 + sl) * Hc) + k4);
            sm.B.w2[tid] = __ldg(&W2[tid]);
        }
        if (tid < 4)  sm.B.lp[tid] = g_lp[b * Nc + g * 4 + tid];
        if (tid < Nc) sm.B.pr[tid] = 0.f;
        __syncthreads();

        // warp = (sl = w>>2, th = (w>>1)&1, kh = w&1): 64-k partial
        const int w = tid >> 5, lane = tid & 31;
        const int sl = w >> 2;
        const int th = (w >> 1) & 1;
        const int kh = w & 1;
        const int t  = th * 32 + lane;
        const int kq0 = kh * 16;

        float acc = 0.f;
        #pragma unroll 8
        for (int kq = kq0; kq < kq0 + 16; kq++) {
            float4 a4 = *(const float4*)&sm.B.a[sl][kq * 4];
            float4 w4 = *(const float4*)&sm.B.w2[kq * 4];
            float b0 = sm.B.bt[kq * 4 + 0][t];
            float b1v= sm.B.bt[kq * 4 + 1][t];
            float b2v= sm.B.bt[kq * 4 + 2][t];
            float b3 = sm.B.bt[kq * 4 + 3][t];
            acc += fmaxf(a4.x + b0, 0.f) * w4.x;
            acc += fmaxf(a4.y + b1v,0.f) * w4.y;
            acc += fmaxf(a4.z + b2v,0.f) * w4.z;
            acc += fmaxf(a4.w + b3, 0.f) * w4.w;
        }
        sm.B.psum[kh][sl][t] = acc;
        __syncthreads();

        // combine halves, store ew, accumulate pressures
        if (tid < 256) {
            int sl2 = tid >> 6, t2 = tid & 63;
            int s = g * 4 + sl2;
            if (t2 != s) {
                float ew = sm.B.psum[0][sl2][t2] + sm.B.psum[1][sl2][t2] + __ldg(b2);
                int e = s * 63 + (t2 < s ? t2 : t2 - 1);
                out[BN + b * E + e] = ew;
                atomicAdd(&sm.B.pr[t2], ew * sm.B.lp[sl2]);
            }
        }
        __syncthreads();
        if (tid < Nc) atomicAdd(out + b * Nc + tid, sm.B.pr[tid]);
    }
}

// ---------------------------------------------------------------------------
extern "C" void kernel_launch(void* const* d_in, const int* in_sizes, int n_in,
                              void* d_out, int out_size)
{
    const float* x    = (const float*)d_in[0];
    const float* Wg   = (const float*)d_in[2];
    const float* bg   = (const float*)d_in[3];
    const float* W1   = (const float*)d_in[4];
    const float* b1   = (const float*)d_in[5];
    const float* W2   = (const float*)d_in[6];
    const float* b2   = (const float*)d_in[7];
    const float* Wgcn = (const float*)d_in[8];
    const float* bgcn = (const float*)d_in[9];
    const float* Wp   = (const float*)d_in[14];
    const float* bp   = (const float*)d_in[15];
    float* out = (float*)d_out;

    const int E = in_sizes[1] / 2;   // 4032 = 64*63 (dense permutations)

    kfused<<<GRID, NTHR>>>(x, Wg, bg, W1, b1, W2, b2,
                           Wgcn, bgcn, Wp, bp, out, E);
}

// round 6
// speedup vs baseline: 1.1132x; 1.1132x over previous
#include <cuda_runtime.h>

// Problem constants (STGNN_91242285236402): B=8, T=16, N=64, F=16, H=128
#define Bc 8
#define Tc 16
#define Nc 64
#define Fc 16
#define Hc 128
#define BN (Bc * Nc)   // 512
#define PADN 68        // padded row width for bt_sh [k][t]
#define GRID 256
#define NTHR 256

// Scratch (allocation-free: __device__ globals)
__device__ float g_a  [BN * Hc];        // a[row][k]   = node@W1s.T + b1
__device__ float g_btT[Bc * Hc * Nc];   // btT[b][k][n] = (node@W1t.T) transposed
__device__ float g_lp [BN];             // Wp . (Wgcn@node + bgcn)
__device__ unsigned g_bar = 0;          // grid barrier (monotonic, replay-safe)

union SmemU {
    struct {
        float x[4][Fc];
        float node[4][Hc];
        float wv2[2][Hc];
        float cb;
    } A;
    struct {
        float bt[Hc][PADN];     // 34.8 KB
        float a[2][Hc];
        float w2[Hc];
        float lp[2];
        float pr[Nc];
        float psum[2][2][Nc];   // [kh][sl][t]
    } B;
};

__device__ __forceinline__ void grid_bar()
{
    __syncthreads();
    __threadfence();
    if (threadIdx.x == 0) {
        unsigned v = atomicAdd(&g_bar, 1u);
        unsigned target = (v & ~(GRID - 1u)) + GRID;   // end of this wave
        volatile unsigned* p = &g_bar;
        while (*p < target) { }
        __threadfence();
    }
    __syncthreads();
}

// ---------------------------------------------------------------------------
// Fused kernel, 256 blocks x 256 threads (2 blocks/SM, all co-resident).
// Phase A: block = (rowgroup rg = blockIdx>>1 [4 rows], bh = blockIdx&1).
//   both : node[h] = bg[h] + sum_f x*Wg          (4 x 128)
//   bh=0 : a[k]  = b1[k] + node.W1s[k] -> g_a ;  pressures init = bp
//   bh=1 : btT[b][k][n] = node.W1t[k]  -> g_btT; wvec, cb, lp -> g_lp
// Phase B: block = (b = blockIdx>>5, g = blockIdx&31 [2 src]); dense edges:
//   warp = (sl, t-half, k-half): 64-k partial -> smem; combine:
//   ew(s,t) = b2 + sum_k relu(a[s,k] + btT[k,t]) * W2[k],  e = s*63+(t-(t>s))
//   pressures[b,t] += ew * lp[s]
// ---------------------------------------------------------------------------
__global__ void __launch_bounds__(NTHR, 2) kfused(
    const float* __restrict__ x,   const float* __restrict__ Wg,
    const float* __restrict__ bg,  const float* __restrict__ W1,
    const float* __restrict__ b1,  const float* __restrict__ W2,
    const float* __restrict__ b2,  const float* __restrict__ Wgcn,
    const float* __restrict__ bgcn,const float* __restrict__ Wp,
    const float* __restrict__ bp,  float* __restrict__ out, int E)
{
    __shared__ SmemU sm;
    const int tid = threadIdx.x;

    // ================= Phase A =================
    {
        const int bh = blockIdx.x & 1;          // 0 -> a, 1 -> btT
        const int rowbase = (blockIdx.x >> 1) * 4;

        // stage x (4 rows x 16 f)
        if (tid < 64) {
            int r = tid >> 4, f = tid & 15;
            int row = rowbase + r, b = row >> 6, n = row & 63;
            sm.A.x[r][f] = x[(((b * Tc + (Tc - 1)) * Nc + n) * Fc) + f];
        }
        if (bh == 0) {
            if (tid < 4) out[rowbase + tid] = __ldg(bp);   // pressures init
        } else {
            // wvec half-partials: thread (h = tid&127, kh = tid>>7)
            int h = tid & 127, kh = tid >> 7;
            float s = 0.f;
            const int k0 = kh * 64;
            #pragma unroll 16
            for (int k = 0; k < 64; k++)
                s += __ldg(&Wp[k0 + k]) * __ldg(&Wgcn[(k0 + k) * Hc + h]);
            sm.A.wv2[kh][h] = s;
            if (tid == 0) sm.A.cb = 0.f;
        }
        __syncthreads();

        // node: 4 rows x 128 h over 256 threads (2 outputs each)
        #pragma unroll
        for (int i = 0; i < 2; i++) {
            int idx = tid + i * NTHR;
            int r = idx >> 7, h = idx & 127;
            const float4* wg4 = (const float4*)(Wg + h * Fc);
            float4 w0 = __ldg(wg4 + 0), w1 = __ldg(wg4 + 1);
            float4 w2 = __ldg(wg4 + 2), w3 = __ldg(wg4 + 3);
            const float* xr = sm.A.x[r];
            float acc = __ldg(&bg[h]);
            acc += xr[0]*w0.x + xr[1]*w0.y + xr[2]*w0.z + xr[3]*w0.w;
            acc += xr[4]*w1.x + xr[5]*w1.y + xr[6]*w1.z + xr[7]*w1.w;
            acc += xr[8]*w2.x + xr[9]*w2.y + xr[10]*w2.z + xr[11]*w2.w;
            acc += xr[12]*w3.x + xr[13]*w3.y + xr[14]*w3.z + xr[15]*w3.w;
            sm.A.node[r][h] = acc;
        }
        if (bh == 1 && tid < 128) {
            // cb reduction
            float v = __ldg(&Wp[tid]) * __ldg(&bgcn[tid]);
            #pragma unroll
            for (int o = 16; o; o >>= 1) v += __shfl_xor_sync(0xffffffffu, v, o);
            if ((tid & 31) == 0) atomicAdd(&sm.A.cb, v);
        }
        __syncthreads();

        // GEMM: 8 warps, warp w owns k in [w*16, w*16+16); 8-lane dots.
        const int lane = tid & 31, w = tid >> 5;
        const int j = lane & 7, d = lane >> 3;
        const float* Wbase = W1 + bh * Hc;

        #pragma unroll
        for (int r = 0; r < 4; r++) {
            const float* nrow = &sm.A.node[r][j * 16];
            float4 n0 = *(const float4*)(nrow + 0);
            float4 n1 = *(const float4*)(nrow + 4);
            float4 n2 = *(const float4*)(nrow + 8);
            float4 n3 = *(const float4*)(nrow + 12);
            #pragma unroll
            for (int kk = 0; kk < 4; kk++) {
                int k = w * 16 + kk * 4 + d;
                const float4* wp4 = (const float4*)(Wbase + k * (2 * Hc) + j * 16);
                float4 w0 = __ldg(wp4 + 0), w1 = __ldg(wp4 + 1);
                float4 w2 = __ldg(wp4 + 2), w3 = __ldg(wp4 + 3);
                float acc = n0.x*w0.x + n0.y*w0.y + n0.z*w0.z + n0.w*w0.w
                          + n1.x*w1.x + n1.y*w1.y + n1.z*w1.z + n1.w*w1.w
                          + n2.x*w2.x + n2.y*w2.y + n2.z*w2.z + n2.w*w2.w
                          + n3.x*w3.x + n3.y*w3.y + n3.z*w3.z + n3.w*w3.w;
                acc += __shfl_xor_sync(0xffffffffu, acc, 1);
                acc += __shfl_xor_sync(0xffffffffu, acc, 2);
                acc += __shfl_xor_sync(0xffffffffu, acc, 4);
                if (j == 0) {
                    int row = rowbase + r;
                    if (bh == 0) {
                        g_a[row * Hc + k] = acc + __ldg(&b1[k]);
                    } else {
                        int b = row >> 6, n = row & 63;
                        g_btT[(b * Hc + k) * Nc + n] = acc;
                    }
                }
            }
        }

        // lp: warps 0..3 reduce rows 0..3 (bh=1 blocks only)
        if (bh == 1 && w < 4) {
            float4 n  = *(const float4*)&sm.A.node[w][lane * 4];
            float4 wa = *(const float4*)&sm.A.wv2[0][lane * 4];
            float4 wb = *(const float4*)&sm.A.wv2[1][lane * 4];
            float v = n.x*(wa.x+wb.x) + n.y*(wa.y+wb.y)
                    + n.z*(wa.z+wb.z) + n.w*(wa.w+wb.w);
            #pragma unroll
            for (int o = 16; o; o >>= 1) v += __shfl_xor_sync(0xffffffffu, v, o);
            if (lane == 0) g_lp[rowbase + w] = v + sm.A.cb;
        }
    }

    // ================= grid barrier =================
    grid_bar();

    // ================= Phase B =================
    {
        const int b = blockIdx.x >> 5;
        const int g = blockIdx.x & 31;

        // stage btT[b] (128 x 64) transposed-padded: 2048 float4 / 256 thr
        const float4* src4 = (const float4*)(g_btT + b * Hc * Nc);
        #pragma unroll
        for (int p = 0; p < 8; p++) {
            int q = tid + p * NTHR;
            int k = q >> 4, t4 = q & 15;
            float4 v = __ldg(src4 + q);
            *(float4*)&sm.B.bt[k][t4 * 4] = v;
        }
        if (tid < 64) {
            int sl = tid >> 5, k4 = tid & 31;
            *(float4*)&sm.B.a[sl][k4 * 4] =
                __ldg((const float4*)(g_a + (b * Nc + g * 2 + sl) * Hc) + k4);
        }
        if (tid < 128) sm.B.w2[tid] = __ldg(&W2[tid]);
        if (tid < 2)   sm.B.lp[tid] = g_lp[b * Nc + g * 2 + tid];
        if (tid < Nc)  sm.B.pr[tid] = 0.f;
        __syncthreads();

        // warp = (sl = w>>2, th = (w>>1)&1, kh = w&1): 64-k partial
        const int w = tid >> 5, lane = tid & 31;
        const int sl = w >> 2;           // 0..1
        const int th = (w >> 1) & 1;
        const int kh = w & 1;
        const int t  = th * 32 + lane;
        const int kq0 = kh * 16;

        float acc = 0.f;
        #pragma unroll 8
        for (int kq = kq0; kq < kq0 + 16; kq++) {
            float4 a4 = *(const float4*)&sm.B.a[sl][kq * 4];
            float4 w4 = *(const float4*)&sm.B.w2[kq * 4];
            float b0 = sm.B.bt[kq * 4 + 0][t];
            float b1v= sm.B.bt[kq * 4 + 1][t];
            float b2v= sm.B.bt[kq * 4 + 2][t];
            float b3 = sm.B.bt[kq * 4 + 3][t];
            acc += fmaxf(a4.x + b0, 0.f) * w4.x;
            acc += fmaxf(a4.y + b1v,0.f) * w4.y;
            acc += fmaxf(a4.z + b2v,0.f) * w4.z;
            acc += fmaxf(a4.w + b3, 0.f) * w4.w;
        }
        sm.B.psum[kh][sl][t] = acc;
        __syncthreads();

        // combine halves, store ew, accumulate pressures
        if (tid < 128) {
            int sl2 = tid >> 6, t2 = tid & 63;
            int s = g * 2 + sl2;
            if (t2 != s) {
                float ew = sm.B.psum[0][sl2][t2] + sm.B.psum[1][sl2][t2] + __ldg(b2);
                int e = s * 63 + (t2 < s ? t2 : t2 - 1);
                out[BN + b * E + e] = ew;
                atomicAdd(&sm.B.pr[t2], ew * sm.B.lp[sl2]);
            }
        }
        __syncthreads();
        if (tid < Nc) atomicAdd(out + b * Nc + tid, sm.B.pr[tid]);
    }
}

// ---------------------------------------------------------------------------
extern "C" void kernel_launch(void* const* d_in, const int* in_sizes, int n_in,
                              void* d_out, int out_size)
{
    const float* x    = (const float*)d_in[0];
    const float* Wg   = (const float*)d_in[2];
    const float* bg   = (const float*)d_in[3];
    const float* W1   = (const float*)d_in[4];
    const float* b1   = (const float*)d_in[5];
    const float* W2   = (const float*)d_in[6];
    const float* b2   = (const float*)d_in[7];
    const float* Wgcn = (const float*)d_in[8];
    const float* bgcn = (const float*)d_in[9];
    const float* Wp   = (const float*)d_in[14];
    const float* bp   = (const float*)d_in[15];
    float* out = (float*)d_out;

    const int E = in_sizes[1] / 2;   // 4032 = 64*63 (dense permutations)

    kfused<<<GRID, NTHR>>>(x, Wg, bg, W1, b1, W2, b2,
                           Wgcn, bgcn, Wp, bp, out, E);
}

// round 8
// speedup vs baseline: 1.2505x; 1.1233x over previous
#include <cuda_runtime.h>

// Problem constants (STGNN_91242285236402): B=8, T=16, N=64, F=16, H=128
#define Bc 8
#define Tc 16
#define Nc 64
#define Fc 16
#define Hc 128
#define BN (Bc * Nc)   // 512
#define GRID 128
#define NTHR 256

// Scratch (allocation-free): btT in k-vectorized layout [b][k>>2][n][k&3]
__device__ float g_bt4[Bc * 32 * Nc * 4];
__device__ unsigned g_bar = 0;          // grid barrier (monotonic, replay-safe)

// ---------------------------------------------------------------------------
// One fused kernel, 128 blocks x 256 threads (all co-resident on 148 SMs).
// Block (b = blockIdx>>4, g = blockIdx&15) owns rows rowbase = blockIdx*4,
// which are BOTH its Phase-A produce set and its Phase-B source nodes.
//   pre-arrive : node[4][128]; btT GEMM (W1t) -> g_bt4 (global)
//   arrive     : grid-barrier ticket (proven monotonic pattern)
//   hidden work: a GEMM (W1s) -> smem; wvec (Wgcn.T@Wp); cb; lp; w2; pr init
//   wait       : spin to wave target
//   post       : stage g_bt4[b] -> smem; dense edge loop:
//     ew(s,t) = b2 + sum_k relu(a[s,k] + btT[k,t]) * W2[k], e = s*63+(t-(t>s))
//     pressures[b,t] += ew * lp[s]
// ---------------------------------------------------------------------------
__global__ void __launch_bounds__(NTHR) kfused(
    const float* __restrict__ x,   const float* __restrict__ Wg,
    const float* __restrict__ bg,  const float* __restrict__ W1,
    const float* __restrict__ b1,  const float* __restrict__ W2,
    const float* __restrict__ b2,  const float* __restrict__ Wgcn,
    const float* __restrict__ bgcn,const float* __restrict__ Wp,
    const float* __restrict__ bp,  float* __restrict__ out, int E)
{
    __shared__ float x_sh[4][Fc];
    __shared__ float node_sh[4][Hc];
    __shared__ float a_sh[4][Hc];
    __shared__ float wv2[2][Hc];
    __shared__ float w2_sh[Hc];
    __shared__ float lp_sh[4];
    __shared__ float pr_sh[Nc];
    __shared__ float bt4_sh[32][Nc][4];   // 32 KB
    __shared__ unsigned s_target;
    __shared__ float cb_sh;

    const int tid = threadIdx.x;
    const int b = blockIdx.x >> 4;
    const int g = blockIdx.x & 15;
    const int rowbase = blockIdx.x * 4;   // = b*64 + g*4

    // ---- stage x (4 rows x 16 f); init pressures (g==0 blocks); cb init
    if (tid < 64) {
        int r = tid >> 4, f = tid & 15;
        int n = (rowbase + r) & 63;
        x_sh[r][f] = x[(((b * Tc + (Tc - 1)) * Nc + n) * Fc) + f];
    }
    if (g == 0 && tid < Nc) out[b * Nc + tid] = __ldg(bp);
    if (tid == 0) cb_sh = 0.f;
    __syncthreads();

    // ---- node: 4 rows x 128 h over 256 threads (2 outputs each)
    #pragma unroll
    for (int i = 0; i < 2; i++) {
        int idx = tid + i * NTHR;
        int r = idx >> 7, h = idx & 127;
        const float4* wg4 = (const float4*)(Wg + h * Fc);
        float4 w0 = __ldg(wg4 + 0), w1 = __ldg(wg4 + 1);
        float4 w2v= __ldg(wg4 + 2), w3 = __ldg(wg4 + 3);
        const float* xr = x_sh[r];
        float acc = __ldg(&bg[h]);
        acc += xr[0]*w0.x + xr[1]*w0.y + xr[2]*w0.z + xr[3]*w0.w;
        acc += xr[4]*w1.x + xr[5]*w1.y + xr[6]*w1.z + xr[7]*w1.w;
        acc += xr[8]*w2v.x+ xr[9]*w2v.y+ xr[10]*w2v.z+ xr[11]*w2v.w;
        acc += xr[12]*w3.x+ xr[13]*w3.y+ xr[14]*w3.z+ xr[15]*w3.w;
        node_sh[r][h] = acc;
    }
    __syncthreads();

    // ---- cache node[4 rows][j*16..+16] in registers (16 float4)
    const int lane = tid & 31, w = tid >> 5;
    const int j = lane & 7, d = lane >> 3;
    float4 nr[4][4];
    #pragma unroll
    for (int r = 0; r < 4; r++)
        #pragma unroll
        for (int c = 0; c < 4; c++)
            nr[r][c] = *(const float4*)&node_sh[r][j * 16 + c * 4];

    // ---- btT GEMM (W1t half): warp w -> k in [w*16,+16); 8-lane dots
    {
        const float* Wt = W1 + Hc;   // W1t
        #pragma unroll
        for (int kk = 0; kk < 4; kk++) {
            int k = w * 16 + kk * 4 + d;
            const float4* wp4 = (const float4*)(Wt + k * (2 * Hc) + j * 16);
            float4 w0 = __ldg(wp4 + 0), w1 = __ldg(wp4 + 1);
            float4 w2v= __ldg(wp4 + 2), w3 = __ldg(wp4 + 3);
            #pragma unroll
            for (int r = 0; r < 4; r++) {
                float acc = nr[r][0].x*w0.x + nr[r][0].y*w0.y + nr[r][0].z*w0.z + nr[r][0].w*w0.w
                          + nr[r][1].x*w1.x + nr[r][1].y*w1.y + nr[r][1].z*w1.z + nr[r][1].w*w1.w
                          + nr[r][2].x*w2v.x+ nr[r][2].y*w2v.y+ nr[r][2].z*w2v.z+ nr[r][2].w*w2v.w
                          + nr[r][3].x*w3.x + nr[r][3].y*w3.y + nr[r][3].z*w3.z + nr[r][3].w*w3.w;
                acc += __shfl_xor_sync(0xffffffffu, acc, 1);
                acc += __shfl_xor_sync(0xffffffffu, acc, 2);
                acc += __shfl_xor_sync(0xffffffffu, acc, 4);
                if (j == 0) {
                    int n = g * 4 + r;
                    g_bt4[((b * 32 + (w * 4 + kk)) * Nc + n) * 4 + d] = acc;
                }
            }
        }
    }

    // ---- barrier ARRIVE (proven monotonic pattern, split arrive/wait)
    __syncthreads();                        // all g_bt4 stores issued
    if (tid == 0) {
        __threadfence();                    // publish before arrival
        unsigned v = atomicAdd(&g_bar, 1u);
        s_target = (v & ~(GRID - 1u)) + GRID;
    }

    // ---- hidden independent work: a GEMM (W1s) -> a_sh
    {
        const float* Ws = W1;   // W1s
        #pragma unroll
        for (int kk = 0; kk < 4; kk++) {
            int k = w * 16 + kk * 4 + d;
            const float4* wp4 = (const float4*)(Ws + k * (2 * Hc) + j * 16);
            float4 w0 = __ldg(wp4 + 0), w1 = __ldg(wp4 + 1);
            float4 w2v= __ldg(wp4 + 2), w3 = __ldg(wp4 + 3);
            #pragma unroll
            for (int r = 0; r < 4; r++) {
                float acc = nr[r][0].x*w0.x + nr[r][0].y*w0.y + nr[r][0].z*w0.z + nr[r][0].w*w0.w
                          + nr[r][1].x*w1.x + nr[r][1].y*w1.y + nr[r][1].z*w1.z + nr[r][1].w*w1.w
                          + nr[r][2].x*w2v.x+ nr[r][2].y*w2v.y+ nr[r][2].z*w2v.z+ nr[r][2].w*w2v.w
                          + nr[r][3].x*w3.x + nr[r][3].y*w3.y + nr[r][3].z*w3.z + nr[r][3].w*w3.w;
                acc += __shfl_xor_sync(0xffffffffu, acc, 1);
                acc += __shfl_xor_sync(0xffffffffu, acc, 2);
                acc += __shfl_xor_sync(0xffffffffu, acc, 4);
                if (j == 0) a_sh[r][k] = acc + __ldg(&b1[k]);
            }
        }
    }

    // ---- wvec half-partials + cb (all local)
    {
        int h = tid & 127, kh = tid >> 7;
        float s = 0.f;
        const int k0 = kh * 64;
        #pragma unroll 16
        for (int k = 0; k < 64; k++)
            s += __ldg(&Wp[k0 + k]) * __ldg(&Wgcn[(k0 + k) * Hc + h]);
        wv2[kh][h] = s;
    }
    if (tid < 128) {
        float v = __ldg(&Wp[tid]) * __ldg(&bgcn[tid]);
        #pragma unroll
        for (int o = 16; o; o >>= 1) v += __shfl_xor_sync(0xffffffffu, v, o);
        if ((tid & 31) == 0) atomicAdd(&cb_sh, v);
    }
    if (tid < 128) w2_sh[tid] = __ldg(&W2[tid]);
    if (tid < Nc)  pr_sh[tid] = 0.f;
    __syncthreads();

    // lp: warps 0..3 reduce node rows 0..3 against wvec
    if (w < 4) {
        float4 n  = *(const float4*)&node_sh[w][lane * 4];
        float4 wa = *(const float4*)&wv2[0][lane * 4];
        float4 wb = *(const float4*)&wv2[1][lane * 4];
        float v = n.x*(wa.x+wb.x) + n.y*(wa.y+wb.y)
                + n.z*(wa.z+wb.z) + n.w*(wa.w+wb.w);
        #pragma unroll
        for (int o = 16; o; o >>= 1) v += __shfl_xor_sync(0xffffffffu, v, o);
        if (lane == 0) lp_sh[w] = v + cb_sh;
    }

    // ---- barrier WAIT
    __syncthreads();                        // s_target visible; local work done
    if (tid == 0) {
        volatile unsigned* p = &g_bar;
        while (*p < s_target) __nanosleep(32);
        __threadfence();                    // acquire
    }
    __syncthreads();

    // ---- stage g_bt4[b] (32 KB) -> bt4_sh
    {
        const float4* src4 = (const float4*)(g_bt4 + b * 32 * Nc * 4);
        #pragma unroll
        for (int p = 0; p < 8; p++) {
            int q = tid + p * NTHR;          // 0..2047
            int k4 = q >> 6, t4 = q & 63;
            *(float4*)&bt4_sh[k4][t4][0] = __ldg(src4 + q);
        }
    }
    __syncthreads();

    // ---- dense edge loop: warp = (sl = w>>1, th = w&1); lane -> t
    {
        const int sl = w >> 1;
        const int t  = (w & 1) * 32 + lane;
        const int s  = g * 4 + sl;

        float acc = 0.f;
        #pragma unroll 8
        for (int kq = 0; kq < 32; kq++) {
            float4 a4 = *(const float4*)&a_sh[sl][kq * 4];    // broadcast
            float4 w4 = *(const float4*)&w2_sh[kq * 4];       // broadcast
            float4 bt = *(const float4*)&bt4_sh[kq][t][0];    // conflict-free
            acc += fmaxf(a4.x + bt.x, 0.f) * w4.x;
            acc += fmaxf(a4.y + bt.y, 0.f) * w4.y;
            acc += fmaxf(a4.z + bt.z, 0.f) * w4.z;
            acc += fmaxf(a4.w + bt.w, 0.f) * w4.w;
        }

        if (t != s) {
            float ew = acc + __ldg(b2);
            int e = s * 63 + (t < s ? t : t - 1);
            out[BN + b * E + e] = ew;
            atomicAdd(&pr_sh[t], ew * lp_sh[sl]);
        }
    }
    __syncthreads();
    if (tid < Nc) atomicAdd(out + b * Nc + tid, pr_sh[tid]);
}

// ---------------------------------------------------------------------------
extern "C" void kernel_launch(void* const* d_in, const int* in_sizes, int n_in,
                              void* d_out, int out_size)
{
    const float* x    = (const float*)d_in[0];
    const float* Wg   = (const float*)d_in[2];
    const float* bg   = (const float*)d_in[3];
    const float* W1   = (const float*)d_in[4];
    const float* b1   = (const float*)d_in[5];
    const float* W2   = (const float*)d_in[6];
    const float* b2   = (const float*)d_in[7];
    const float* Wgcn = (const float*)d_in[8];
    const float* bgcn = (const float*)d_in[9];
    const float* Wp   = (const float*)d_in[14];
    const float* bp   = (const float*)d_in[15];
    float* out = (float*)d_out;

    const int E = in_sizes[1] / 2;   // 4032 = 64*63 (dense permutations)

    kfused<<<GRID, NTHR>>>(x, Wg, bg, W1, b1, W2, b2,
                           Wgcn, bgcn, Wp, bp, out, E);
}